// round 14
// baseline (speedup 1.0000x reference)
#include <cuda_runtime.h>
#include <cuda_fp16.h>
#include <cstdint>

#define B_SZ    16
#define C_IN    64
#define N_POS   40962
#define C_OUT   32
#define K_CH    224                 // 7*C_OUT, permuted: k = sub*32 + o
#define NEW_N   (4*N_POS - 6)       // 163842
#define TILE_P  64
#define TILES_PER_B 641             // ceil(40962/64)
#define WORK_ITEMS (B_SZ * TILES_PER_B)   // 10256
#define GEMM_GRID 444               // 148 SMs x 3 CTAs
#define GEMM_THREADS 256

// 293 MB scratch for y' [B][N][224] fp16 (permuted channel layout)
__device__ __half g_y[(size_t)B_SZ * N_POS * K_CH];

// ---------------------------------------------------------------------------
// smem layout (bytes). 66.5 KB -> 3 CTAs/SM.
// UNION holds x-staging f32 [64][64] (16384 B) during load/convert, then the
// epilogue fp16 stage [64][232] (29696 B) during MMA/writeback.
// ---------------------------------------------------------------------------
#define SM_XH    0        // xh [64][64] fp16 : 8192 (SW128)
#define SM_WH    8192     // wh [224][64] fp16 : 28672 (SW128)
#define SM_BIAS  36864    // bias f32 [224] : 896
#define SM_UNION 37760    // max(16384, 29696) = 29696
#define STG_ROW_H 232
#define SM_TOTAL 67584

static __device__ __forceinline__ uint32_t smem_u32(const void* p) {
    uint32_t a;
    asm("{ .reg .u64 t; cvta.to.shared.u64 t, %1; cvt.u32.u64 %0, t; }" : "=r"(a) : "l"(p));
    return a;
}
static __device__ __forceinline__ uint32_t swz(uint32_t off) {
    return off ^ ((off >> 3) & 0x70);
}
static __device__ __forceinline__ void ldsm_x4(uint32_t* a, uint32_t addr) {
    asm volatile("ldmatrix.sync.aligned.m8n8.x4.shared.b16 {%0,%1,%2,%3}, [%4];"
                 : "=r"(a[0]), "=r"(a[1]), "=r"(a[2]), "=r"(a[3]) : "r"(addr));
}
static __device__ __forceinline__ void ldsm_x2(uint32_t* b, uint32_t addr) {
    asm volatile("ldmatrix.sync.aligned.m8n8.x2.shared.b16 {%0,%1}, [%2];"
                 : "=r"(b[0]), "=r"(b[1]) : "r"(addr));
}
static __device__ __forceinline__ void mma_f16(float* d, const uint32_t* a, const uint32_t* b) {
    asm volatile("mma.sync.aligned.m16n8k16.row.col.f32.f16.f16.f32 "
                 "{%0,%1,%2,%3}, {%4,%5,%6,%7}, {%8,%9}, {%0,%1,%2,%3};"
                 : "+f"(d[0]), "+f"(d[1]), "+f"(d[2]), "+f"(d[3])
                 : "r"(a[0]), "r"(a[1]), "r"(a[2]), "r"(a[3]), "r"(b[0]), "r"(b[1]));
}

// ---------------------------------------------------------------------------
// Persistent HMMA GEMM: y'[b][p][n] = sum_c x[b][c][p]*wh[n][c] + bias(n)
// 256 threads / 8 warps, 64x224 tile, 3 CTAs/SM.
// Warp: rows wm*16..+15 (wm=w&3); two n-passes of 56 cols (wq=w>>2, np=0/1
// -> col base wq*112 + np*56). Acc 28 f32 live per pass.
// ---------------------------------------------------------------------------
__global__ void __launch_bounds__(GEMM_THREADS, 3)
gemm_hmma_kernel(const float* __restrict__ x,
                 const float* __restrict__ W,
                 const float* __restrict__ bias)
{
    extern __shared__ char sm[];
    const uint32_t smb = smem_u32(sm);
    float*  Asf = (float*)(sm + SM_UNION);
    __half* stg = (__half*)(sm + SM_UNION);
    float*  bSm = (float*)(sm + SM_BIAS);

    const int tid = threadIdx.x;
    const int w   = tid >> 5;
    const int l   = tid & 31;
    const int wm  = w & 3;           // 16-row group
    const int wq  = w >> 2;          // 0..1 : 112-col half

    // --- one-time: build wh (permuted, fp16, swizzled) + bias table ---
    for (int idx = tid; idx < K_CH * C_IN; idx += GEMM_THREADS) {
        int n = idx >> 6, c = idx & 63;
        int rw = (n & 31) * 7 + (n >> 5);
        uint32_t off = swz((uint32_t)(n * 128 + c * 2));
        *(__half*)(sm + SM_WH + off) = __float2half_rn(W[rw * C_IN + c]);
    }
    if (tid < K_CH) bSm[tid] = bias[(tid & 31) * 7 + (tid >> 5)];

    const uint32_t a_lane = (uint32_t)((wm * 16 + (l & 15)) * 128 + (l >> 4) * 16);

    const int cp  = tid & 63;        // convert row
    const int cc0 = (tid >> 6) * 16; // convert c range

    __syncthreads();

    for (int item = blockIdx.x; item < WORK_ITEMS; item += GEMM_GRID) {
        const int b  = item / TILES_PER_B;
        const int t  = item - b * TILES_PER_B;
        const int p0 = t * TILE_P;
        const float* xb = x + (size_t)b * C_IN * N_POS;
        __half* yb = g_y + (size_t)b * N_POS * K_CH;

        // --- stage Asf[c][p] (64x64) into UNION ---
        #pragma unroll
        for (int it2 = 0; it2 < 16; it2++) {
            int idx = it2 * GEMM_THREADS + tid;
            int c = idx >> 6, p = idx & 63;
            Asf[idx] = (p0 + p < N_POS) ? xb[(size_t)c * N_POS + p0 + p] : 0.0f;
        }
        __syncthreads();

        // --- convert: xh [p][c] fp16, swizzled ---
        #pragma unroll
        for (int blk = 0; blk < 2; blk++) {
            int cb = cc0 + blk * 8;
            float xv[8];
            #pragma unroll
            for (int j = 0; j < 8; j++) xv[j] = Asf[(cb + j) * TILE_P + cp];
            uint32_t hi[4];
            #pragma unroll
            for (int q = 0; q < 4; q++) {
                half2 h = __floats2half2_rn(xv[2 * q], xv[2 * q + 1]);
                hi[q] = *(uint32_t*)&h;
            }
            uint32_t off = swz((uint32_t)(cp * 128 + cb * 2));
            *(uint4*)(sm + SM_XH + off) = make_uint4(hi[0], hi[1], hi[2], hi[3]);
        }
        __syncthreads();   // XH ready; Asf dead -> UNION becomes stage

        // --- two n-passes: MMA + epilogue STS ---
        #pragma unroll
        for (int np = 0; np < 2; np++) {
            const int cbase = wq * 112 + np * 56;
            const uint32_t b_lane = (uint32_t)((cbase + (l & 7)) * 128 + ((l >> 3) & 1) * 16);

            float d[7][4];
            #pragma unroll
            for (int nt = 0; nt < 7; nt++)
                #pragma unroll
                for (int q = 0; q < 4; q++) d[nt][q] = 0.0f;

            #pragma unroll
            for (int kci = 0; kci < 4; kci++) {
                const uint32_t kcb = kci * 32;
                uint32_t bfr[7][2];
                #pragma unroll
                for (int nt = 0; nt < 7; nt++)
                    ldsm_x2(bfr[nt], smb + SM_WH + swz(b_lane + (uint32_t)nt * 1024 + kcb));
                uint32_t ah[4];
                ldsm_x4(ah, smb + SM_XH + swz(a_lane + kcb));
                #pragma unroll
                for (int nt = 0; nt < 7; nt++)
                    mma_f16(d[nt], ah, bfr[nt]);
            }

            // epilogue STS: bias (smem) + fp16 pack
            {
                const int qrow = l >> 2;
                const int ncol = cbase + (l & 3) * 2;
                #pragma unroll
                for (int rsel = 0; rsel < 2; rsel++) {
                    int row = wm * 16 + rsel * 8 + qrow;
                    __half* sr = stg + row * STG_ROW_H + ncol;
                    #pragma unroll
                    for (int nt = 0; nt < 7; nt++) {
                        float2 bv = *(const float2*)(bSm + ncol + nt * 8);
                        float vx = d[nt][rsel * 2 + 0] + bv.x;
                        float vy = d[nt][rsel * 2 + 1] + bv.y;
                        *(half2*)(sr + nt * 8) = __floats2half2_rn(vx, vy);
                    }
                }
            }
        }
        __syncthreads();   // stage complete

        // --- coalesced writeback: warp w -> rows w*8..+7 (448B rows) ---
        if (l < 28) {
            #pragma unroll
            for (int r = 0; r < 8; r++) {
                int row = w * 8 + r;
                int gp = p0 + row;
                if (gp < N_POS) {
                    uint4 v = *(const uint4*)(stg + row * STG_ROW_H + l * 8);
                    *(uint4*)(yb + (size_t)gp * K_CH + l * 8) = v;
                }
            }
        }
        __syncthreads();   // stage reads done -> UNION reusable as Asf
    }
}

// ---------------------------------------------------------------------------
// Kernel 2: gather (R10/R11 batched-MLP version, 128us, near its BW floor).
// ---------------------------------------------------------------------------
#define GM 256

__global__ void __launch_bounds__(256, 3)
gather_kernel(const int* __restrict__ top,
              const int* __restrict__ down,
              float* __restrict__ out)
{
    __shared__ float smx[GM][33];
    const int b    = blockIdx.y;
    const int m0   = blockIdx.x * GM;
    const int tid  = threadIdx.x;
    const int lane = tid & 31;
    const int w    = tid >> 5;
    const int g8   = lane >> 2;    // 0..7 : m within octet
    const int l4   = lane & 3;     // 0..3 : uint4 slot (8 halves)

    const __half* yb = g_y + (size_t)b * N_POS * K_CH;

    // --- phase 1: index loads (batched) ---
    int jx[4], jy[4];
    #pragma unroll
    for (int i = 0; i < 4; i++) {
        int m = m0 + w * 32 + i * 8 + g8;
        jx[i] = -1; jy[i] = -1;
        if (m < NEW_N) {
            if (m < N_POS) {
                jx[i] = __ldg(top + m);
            } else {
                int2 jj = *(const int2*)(down + 2 * (m - N_POS));
                jx[i] = jj.x; jy[i] = jj.y;
            }
        }
    }

    // --- phase 2: value loads (up to 8 uint4 in flight) ---
    uint4 v0[4], v1[4];
    #pragma unroll
    for (int i = 0; i < 4; i++) {
        v0[i] = make_uint4(0u, 0u, 0u, 0u);
        if (jx[i] >= 0) {
            int s = jx[i] / N_POS, p = jx[i] - s * N_POS;
            v0[i] = *(const uint4*)(yb + (size_t)p * K_CH + s * 32 + l4 * 8);
        }
    }
    #pragma unroll
    for (int i = 0; i < 4; i++) {
        if (jy[i] >= 0) {
            int s = jy[i] / N_POS, p = jy[i] - s * N_POS;
            v1[i] = *(const uint4*)(yb + (size_t)p * K_CH + s * 32 + l4 * 8);
        }
    }

    // --- phase 3: convert + STS ---
    #pragma unroll
    for (int i = 0; i < 4; i++) {
        int mm = w * 32 + i * 8 + g8;
        float vf[8];
        const half2* h0 = (const half2*)&v0[i];
        #pragma unroll
        for (int q = 0; q < 4; q++) {
            float2 f = __half22float2(h0[q]);
            vf[2 * q] = f.x; vf[2 * q + 1] = f.y;
        }
        if (jy[i] >= 0) {
            const half2* h1 = (const half2*)&v1[i];
            #pragma unroll
            for (int q = 0; q < 4; q++) {
                float2 f = __half22float2(h1[q]);
                vf[2 * q]     = 0.5f * (vf[2 * q] + f.x);
                vf[2 * q + 1] = 0.5f * (vf[2 * q + 1] + f.y);
            }
        }
        float* s = &smx[mm][l4 * 8];
        #pragma unroll
        for (int j = 0; j < 8; j++) s[j] = vf[j];
    }
    __syncthreads();

    // --- transpose write: out[b][o][m], float2 along m ---
    float* ob = out + (size_t)b * C_OUT * NEW_N;
    #pragma unroll
    for (int it = 0; it < C_OUT * (GM / 2) / 256; it++) {
        int idx = it * 256 + tid;
        int o = idx >> 7;
        int q = idx & 127;
        int m = m0 + 2 * q;
        if (m < NEW_N) {
            float2 v = make_float2(smx[2 * q][o], smx[2 * q + 1][o]);
            *(float2*)(ob + (size_t)o * NEW_N + m) = v;
        }
    }
}

// ---------------------------------------------------------------------------
extern "C" void kernel_launch(void* const* d_in, const int* in_sizes, int n_in,
                              void* d_out, int out_size)
{
    const float* x    = (const float*)d_in[0];
    const float* W    = (const float*)d_in[1];
    const float* bias = (const float*)d_in[2];
    const int*   top  = (const int*)d_in[3];
    const int*   down = (const int*)d_in[4];
    float* out = (float*)d_out;

    cudaFuncSetAttribute(gemm_hmma_kernel,
                         cudaFuncAttributeMaxDynamicSharedMemorySize, SM_TOTAL);

    gemm_hmma_kernel<<<GEMM_GRID, GEMM_THREADS, SM_TOTAL>>>(x, W, bias);

    dim3 g2((NEW_N + GM - 1) / GM, B_SZ);   // (641, 16)
    gather_kernel<<<g2, 256>>>(top, down, out);
}

// round 15
// speedup vs baseline: 1.1694x; 1.1694x over previous
#include <cuda_runtime.h>
#include <cuda_fp16.h>
#include <cstdint>

#define B_SZ    16
#define C_IN    64
#define N_POS   40962
#define C_OUT   32
#define K_CH    224                 // 7*C_OUT, permuted: k = sub*32 + o
#define NEW_N   (4*N_POS - 6)       // 163842
#define TILE_P  64
#define TILES_PER_B 641             // ceil(40962/64)
#define WORK_ITEMS (B_SZ * TILES_PER_B)   // 10256
#define GEMM_GRID 296
#define GEMM_THREADS 256

// 293 MB scratch for y' [B][N][224] fp16 (permuted channel layout)
__device__ __half g_y[(size_t)B_SZ * N_POS * K_CH];

// ---------------------------------------------------------------------------
// smem layout (bytes). fp16 tiles are [row][64] = 128 B/row, SW128 swizzle.
// Total 82 KB -> 2 CTAs/SM co-resident (phase overlap across CTAs).
// ---------------------------------------------------------------------------
#define SM_XH    0        // xh [64][64] fp16 : 8192
#define SM_WH    8192     // wh [224][64] fp16 : 28672
#define SM_ASF   36864    // x staging f32 [64 c][64 p] : 16384
#define SM_STAGE 53248    // epilogue stage fp16 [64][232] : 29696 (464B rows)
#define STG_ROW_H 232
#define SM_TOTAL 82944

static __device__ __forceinline__ uint32_t smem_u32(const void* p) {
    uint32_t a;
    asm("{ .reg .u64 t; cvta.to.shared.u64 t, %1; cvt.u32.u64 %0, t; }" : "=r"(a) : "l"(p));
    return a;
}
static __device__ __forceinline__ uint32_t swz(uint32_t off) {
    return off ^ ((off >> 3) & 0x70);
}
static __device__ __forceinline__ void ldsm_x4(uint32_t* a, uint32_t addr) {
    asm volatile("ldmatrix.sync.aligned.m8n8.x4.shared.b16 {%0,%1,%2,%3}, [%4];"
                 : "=r"(a[0]), "=r"(a[1]), "=r"(a[2]), "=r"(a[3]) : "r"(addr));
}
static __device__ __forceinline__ void ldsm_x2(uint32_t* b, uint32_t addr) {
    asm volatile("ldmatrix.sync.aligned.m8n8.x2.shared.b16 {%0,%1}, [%2];"
                 : "=r"(b[0]), "=r"(b[1]) : "r"(addr));
}
static __device__ __forceinline__ void mma_f16(float* d, const uint32_t* a, const uint32_t* b) {
    asm volatile("mma.sync.aligned.m16n8k16.row.col.f32.f16.f16.f32 "
                 "{%0,%1,%2,%3}, {%4,%5,%6,%7}, {%8,%9}, {%0,%1,%2,%3};"
                 : "+f"(d[0]), "+f"(d[1]), "+f"(d[2]), "+f"(d[3])
                 : "r"(a[0]), "r"(a[1]), "r"(a[2]), "r"(a[3]), "r"(b[0]), "r"(b[1]));
}
static __device__ __forceinline__ void stg_cs_v4(void* p, uint4 v) {
    asm volatile("st.global.cs.v4.b32 [%0], {%1,%2,%3,%4};"
                 :: "l"(p), "r"(v.x), "r"(v.y), "r"(v.z), "r"(v.w) : "memory");
}
static __device__ __forceinline__ void stg_cs_v2f(float* p, float2 v) {
    asm volatile("st.global.cs.v2.f32 [%0], {%1,%2};"
                 :: "l"(p), "f"(v.x), "f"(v.y) : "memory");
}

// ---------------------------------------------------------------------------
// Persistent HMMA GEMM: y'[b][p][n] = sum_c x[b][c][p]*wh[n][c] + bias(n)
// Single fp16 segment. 256 threads / 8 warps, 64x224 tile, 2 CTAs/SM.
// Batches processed in REVERSE order so the last-written planes (b~5..0)
// are L2-resident when the gather (which starts at b=0) launches.
// ---------------------------------------------------------------------------
__global__ void __launch_bounds__(GEMM_THREADS, 2)
gemm_hmma_kernel(const float* __restrict__ x,
                 const float* __restrict__ W,
                 const float* __restrict__ bias)
{
    extern __shared__ char sm[];
    const uint32_t smb = smem_u32(sm);
    float*  Asf = (float*)(sm + SM_ASF);
    __half* stg = (__half*)(sm + SM_STAGE);

    const int tid = threadIdx.x;
    const int w   = tid >> 5;
    const int l   = tid & 31;
    const int wm  = w & 1;           // 0..1 : 32-row group
    const int wn  = w >> 1;          // 0..3 : 56-col group

    // --- one-time: build wh (permuted, fp16, swizzled) ---
    for (int idx = tid; idx < K_CH * C_IN; idx += GEMM_THREADS) {
        int n = idx >> 6, c = idx & 63;
        int rw = (n & 31) * 7 + (n >> 5);
        uint32_t off = swz((uint32_t)(n * 128 + c * 2));
        *(__half*)(sm + SM_WH + off) = __float2half_rn(W[rw * C_IN + c]);
    }

    // --- per-thread bias regs: n = wn*56 + nt*8 + 2*(l&3) ---
    float2 bb[7];
    {
        int nbase = wn * 56 + (l & 3) * 2;
        #pragma unroll
        for (int nt = 0; nt < 7; nt++) {
            int n0 = nbase + nt * 8;
            int n1 = n0 + 1;
            bb[nt].x = bias[(n0 & 31) * 7 + (n0 >> 5)];
            bb[nt].y = bias[(n1 & 31) * 7 + (n1 >> 5)];
        }
    }

    const uint32_t a_lane = (uint32_t)((wm * 32 + (l & 15)) * 128 + (l >> 4) * 16);
    const uint32_t b_lane = (uint32_t)((wn * 56 + (l & 7)) * 128 + ((l >> 3) & 1) * 16);

    const int cp  = tid & 63;        // convert row
    const int cc0 = (tid >> 6) * 16; // convert c range

    int item = blockIdx.x;

    // prologue: stage first tile (reverse batch order, streaming x loads)
    if (item < WORK_ITEMS) {
        int b = B_SZ - 1 - item / TILES_PER_B;
        int t = item % TILES_PER_B;
        const float* xb = x + (size_t)b * C_IN * N_POS;
        int p0 = t * TILE_P;
        #pragma unroll
        for (int it2 = 0; it2 < 16; it2++) {
            int idx = it2 * GEMM_THREADS + tid;
            int c = idx >> 6, p = idx & 63;
            Asf[idx] = (p0 + p < N_POS) ? __ldcs(xb + (size_t)c * N_POS + p0 + p) : 0.0f;
        }
    }
    __syncthreads();

    for (; item < WORK_ITEMS; item += GEMM_GRID) {
        const int b  = B_SZ - 1 - item / TILES_PER_B;
        const int t  = item % TILES_PER_B;
        const int p0 = t * TILE_P;
        __half* yb = g_y + (size_t)b * N_POS * K_CH;

        // --- convert: xh [p][c] fp16, swizzled (reads Asf) ---
        #pragma unroll
        for (int blk = 0; blk < 2; blk++) {
            int cb = cc0 + blk * 8;
            float xv[8];
            #pragma unroll
            for (int j = 0; j < 8; j++) xv[j] = Asf[(cb + j) * TILE_P + cp];
            uint32_t hi[4];
            #pragma unroll
            for (int q = 0; q < 4; q++) {
                half2 h = __floats2half2_rn(xv[2 * q], xv[2 * q + 1]);
                hi[q] = *(uint32_t*)&h;
            }
            uint32_t off = swz((uint32_t)(cp * 128 + cb * 2));
            *(uint4*)(sm + SM_XH + off) = make_uint4(hi[0], hi[1], hi[2], hi[3]);
        }
        __syncthreads();   // xh ready; Asf reads complete

        // --- prefetch next tile's x into Asf (overlaps MMA + epilogue) ---
        {
            int nxt = item + GEMM_GRID;
            if (nxt < WORK_ITEMS) {
                int nb = B_SZ - 1 - nxt / TILES_PER_B;
                int ntl = nxt % TILES_PER_B;
                const float* xb = x + (size_t)nb * C_IN * N_POS;
                int np0 = ntl * TILE_P;
                #pragma unroll
                for (int it2 = 0; it2 < 16; it2++) {
                    int idx = it2 * GEMM_THREADS + tid;
                    int c = idx >> 6, p = idx & 63;
                    Asf[idx] = (np0 + p < N_POS) ? __ldcs(xb + (size_t)c * N_POS + np0 + p) : 0.0f;
                }
            }
        }

        // --- MMA: 4 k16-chunks, single segment ---
        float d[2][7][4];
        #pragma unroll
        for (int mt = 0; mt < 2; mt++)
            #pragma unroll
            for (int nt = 0; nt < 7; nt++)
                #pragma unroll
                for (int q = 0; q < 4; q++) d[mt][nt][q] = 0.0f;

        #pragma unroll
        for (int kci = 0; kci < 4; kci++) {
            const uint32_t kcb = kci * 32;
            uint32_t bfr[7][2];
            #pragma unroll
            for (int nt = 0; nt < 7; nt++)
                ldsm_x2(bfr[nt], smb + SM_WH + swz(b_lane + (uint32_t)nt * 1024 + kcb));
            uint32_t ah[2][4];
            ldsm_x4(ah[0], smb + SM_XH + swz(a_lane + kcb));
            ldsm_x4(ah[1], smb + SM_XH + swz(a_lane + 2048 + kcb));
            #pragma unroll
            for (int nt = 0; nt < 7; nt++) {
                mma_f16(d[0][nt], ah[0], bfr[nt]);
                mma_f16(d[1][nt], ah[1], bfr[nt]);
            }
        }

        // --- epilogue stage: bias + fp16 pack -> smem ---
        {
            const int qrow = l >> 2;
            const int ncol = wn * 56 + (l & 3) * 2;
            #pragma unroll
            for (int mt = 0; mt < 2; mt++) {
                #pragma unroll
                for (int rsel = 0; rsel < 2; rsel++) {
                    int row = wm * 32 + mt * 16 + rsel * 8 + qrow;
                    __half* sr = stg + row * STG_ROW_H + ncol;
                    #pragma unroll
                    for (int nt = 0; nt < 7; nt++) {
                        float vx = d[mt][nt][rsel * 2 + 0] + bb[nt].x;
                        float vy = d[mt][nt][rsel * 2 + 1] + bb[nt].y;
                        *(half2*)(sr + nt * 8) = __floats2half2_rn(vx, vy);
                    }
                }
            }
        }
        __syncthreads();

        // --- coalesced writeback: warp w -> rows w*8..+7 (448B rows) ---
        if (l < 28) {
            #pragma unroll
            for (int r = 0; r < 8; r++) {
                int row = w * 8 + r;
                int gp = p0 + row;
                if (gp < N_POS) {
                    uint4 v = *(const uint4*)(stg + row * STG_ROW_H + l * 8);
                    *(uint4*)(yb + (size_t)gp * K_CH + l * 8) = v;
                }
            }
        }
        __syncthreads();
    }
}

// ---------------------------------------------------------------------------
// Kernel 2: gather (R10/R11 batched-MLP). out stores streamed (evict-first)
// so they don't evict the L2-resident y' planes being read.
// ---------------------------------------------------------------------------
#define GM 256

__global__ void __launch_bounds__(256, 3)
gather_kernel(const int* __restrict__ top,
              const int* __restrict__ down,
              float* __restrict__ out)
{
    __shared__ float smx[GM][33];
    const int b    = blockIdx.y;
    const int m0   = blockIdx.x * GM;
    const int tid  = threadIdx.x;
    const int lane = tid & 31;
    const int w    = tid >> 5;
    const int g8   = lane >> 2;    // 0..7 : m within octet
    const int l4   = lane & 3;     // 0..3 : uint4 slot (8 halves)

    const __half* yb = g_y + (size_t)b * N_POS * K_CH;

    // --- phase 1: index loads (batched) ---
    int jx[4], jy[4];
    #pragma unroll
    for (int i = 0; i < 4; i++) {
        int m = m0 + w * 32 + i * 8 + g8;
        jx[i] = -1; jy[i] = -1;
        if (m < NEW_N) {
            if (m < N_POS) {
                jx[i] = __ldg(top + m);
            } else {
                int2 jj = *(const int2*)(down + 2 * (m - N_POS));
                jx[i] = jj.x; jy[i] = jj.y;
            }
        }
    }

    // --- phase 2: value loads (up to 8 uint4 in flight) ---
    uint4 v0[4], v1[4];
    #pragma unroll
    for (int i = 0; i < 4; i++) {
        v0[i] = make_uint4(0u, 0u, 0u, 0u);
        if (jx[i] >= 0) {
            int s = jx[i] / N_POS, p = jx[i] - s * N_POS;
            v0[i] = *(const uint4*)(yb + (size_t)p * K_CH + s * 32 + l4 * 8);
        }
    }
    #pragma unroll
    for (int i = 0; i < 4; i++) {
        if (jy[i] >= 0) {
            int s = jy[i] / N_POS, p = jy[i] - s * N_POS;
            v1[i] = *(const uint4*)(yb + (size_t)p * K_CH + s * 32 + l4 * 8);
        }
    }

    // --- phase 3: convert + STS ---
    #pragma unroll
    for (int i = 0; i < 4; i++) {
        int mm = w * 32 + i * 8 + g8;
        float vf[8];
        const half2* h0 = (const half2*)&v0[i];
        #pragma unroll
        for (int q = 0; q < 4; q++) {
            float2 f = __half22float2(h0[q]);
            vf[2 * q] = f.x; vf[2 * q + 1] = f.y;
        }
        if (jy[i] >= 0) {
            const half2* h1 = (const half2*)&v1[i];
            #pragma unroll
            for (int q = 0; q < 4; q++) {
                float2 f = __half22float2(h1[q]);
                vf[2 * q]     = 0.5f * (vf[2 * q] + f.x);
                vf[2 * q + 1] = 0.5f * (vf[2 * q + 1] + f.y);
            }
        }
        float* s = &smx[mm][l4 * 8];
        #pragma unroll
        for (int j = 0; j < 8; j++) s[j] = vf[j];
    }
    __syncthreads();

    // --- transpose write: out[b][o][m], float2 along m, streaming stores ---
    float* ob = out + (size_t)b * C_OUT * NEW_N;
    #pragma unroll
    for (int it = 0; it < C_OUT * (GM / 2) / 256; it++) {
        int idx = it * 256 + tid;
        int o = idx >> 7;
        int q = idx & 127;
        int m = m0 + 2 * q;
        if (m < NEW_N) {
            float2 v = make_float2(smx[2 * q][o], smx[2 * q + 1][o]);
            stg_cs_v2f(ob + (size_t)o * NEW_N + m, v);
        }
    }
}

// ---------------------------------------------------------------------------
extern "C" void kernel_launch(void* const* d_in, const int* in_sizes, int n_in,
                              void* d_out, int out_size)
{
    const float* x    = (const float*)d_in[0];
    const float* W    = (const float*)d_in[1];
    const float* bias = (const float*)d_in[2];
    const int*   top  = (const int*)d_in[3];
    const int*   down = (const int*)d_in[4];
    float* out = (float*)d_out;

    cudaFuncSetAttribute(gemm_hmma_kernel,
                         cudaFuncAttributeMaxDynamicSharedMemorySize, SM_TOTAL);

    gemm_hmma_kernel<<<GEMM_GRID, GEMM_THREADS, SM_TOTAL>>>(x, W, bias);

    dim3 g2((NEW_N + GM - 1) / GM, B_SZ);   // (641, 16)
    gather_kernel<<<g2, 256>>>(top, down, out);
}